// round 4
// baseline (speedup 1.0000x reference)
#include <cuda_runtime.h>

// Problem constants (B=1, N=4, C=16, D=64, H=128, W=128)
#define NCTX 4
#define CH   16
#define VOX  (64 * 128 * 128)   // 1,048,576 voxels
#define VPT  2                  // voxels per thread (float2)
#define TPB  256

__global__ __launch_bounds__(TPB, 5) void volattn3d_kernel(
    const float* __restrict__ q,      // [C][V]
    const float* __restrict__ k,      // [N][C][V]
    const float* __restrict__ v,      // [N][C][V]
    const float* __restrict__ w_proj, // [C][C]
    const float* __restrict__ b_proj, // [C]
    float* __restrict__ out)          // [C][V]
{
    __shared__ float sw[CH * CH];
    __shared__ float sb[CH];
    {
        int t = threadIdx.x;
        if (t < CH * CH) sw[t] = w_proj[t];
        if (t < CH)      sb[t] = b_proj[t];
    }
    __syncthreads();

    const int p = (blockIdx.x * TPB + threadIdx.x) * VPT;   // base voxel pair
    const float* qp = q + p;
    const float* kp = k + p;
    const float* vp = v + p;

    // ---- scores[n] = (q . k_n), c-outer so q is never array-resident ----
    float2 sc[NCTX];
#pragma unroll
    for (int n = 0; n < NCTX; ++n) sc[n] = make_float2(0.f, 0.f);

#pragma unroll
    for (int c = 0; c < CH; ++c) {
        const float2 qv = __ldcs(reinterpret_cast<const float2*>(qp + c * VOX));
#pragma unroll
        for (int n = 0; n < NCTX; ++n) {
            const float2 kv = __ldcs(reinterpret_cast<const float2*>(kp + (n * CH + c) * VOX));
            sc[n].x = fmaf(qv.x, kv.x, sc[n].x);
            sc[n].y = fmaf(qv.y, kv.y, sc[n].y);
        }
    }

    // ---- prefetch first v slab (c=0, all n) to overlap the softmax chain ----
    float2 vpre[NCTX];
#pragma unroll
    for (int n = 0; n < NCTX; ++n)
        vpre[n] = __ldcs(reinterpret_cast<const float2*>(vp + (n * CH + 0) * VOX));

    // ---- softmax over n (scale 1/sqrt(16) = 0.25) ----
#pragma unroll
    for (int n = 0; n < NCTX; ++n) { sc[n].x *= 0.25f; sc[n].y *= 0.25f; }

    float2 mx = sc[0];
#pragma unroll
    for (int n = 1; n < NCTX; ++n) {
        mx.x = fmaxf(mx.x, sc[n].x);
        mx.y = fmaxf(mx.y, sc[n].y);
    }
    float2 ssum = make_float2(0.f, 0.f);
#pragma unroll
    for (int n = 0; n < NCTX; ++n) {
        sc[n].x = __expf(sc[n].x - mx.x);
        sc[n].y = __expf(sc[n].y - mx.y);
        ssum.x += sc[n].x;
        ssum.y += sc[n].y;
    }
    const float2 rs = make_float2(__frcp_rn(ssum.x), __frcp_rn(ssum.y));
#pragma unroll
    for (int n = 0; n < NCTX; ++n) { sc[n].x *= rs.x; sc[n].y *= rs.y; }

    // ---- x[c] = sum_n attn[n] * v[n][c] ----
    float2 x[CH];
    // c = 0 uses the prefetched slab
    {
        float2 a = make_float2(0.f, 0.f);
#pragma unroll
        for (int n = 0; n < NCTX; ++n) {
            a.x = fmaf(sc[n].x, vpre[n].x, a.x);
            a.y = fmaf(sc[n].y, vpre[n].y, a.y);
        }
        x[0] = a;
    }
#pragma unroll
    for (int c = 1; c < CH; ++c) {
        float2 a = make_float2(0.f, 0.f);
#pragma unroll
        for (int n = 0; n < NCTX; ++n) {
            const float2 vv = __ldcs(reinterpret_cast<const float2*>(vp + (n * CH + c) * VOX));
            a.x = fmaf(sc[n].x, vv.x, a.x);
            a.y = fmaf(sc[n].y, vv.y, a.y);
        }
        x[c] = a;
    }

    // ---- out[o] = sum_c w[o][c] * x[c] + b[o] ----
    float* op = out + p;
#pragma unroll
    for (int o = 0; o < CH; ++o) {
        const float bo = sb[o];
        float2 acc = make_float2(bo, bo);
#pragma unroll
        for (int c = 0; c < CH; ++c) {
            const float wv = sw[o * CH + c];
            acc.x = fmaf(wv, x[c].x, acc.x);
            acc.y = fmaf(wv, x[c].y, acc.y);
        }
        __stcs(reinterpret_cast<float2*>(op + o * VOX), acc);
    }
}

extern "C" void kernel_launch(void* const* d_in, const int* in_sizes, int n_in,
                              void* d_out, int out_size) {
    const float* q      = (const float*)d_in[0];
    const float* k      = (const float*)d_in[1];
    const float* v      = (const float*)d_in[2];
    const float* w_proj = (const float*)d_in[3];
    const float* b_proj = (const float*)d_in[4];
    float* out = (float*)d_out;

    const int threads = VOX / VPT;            // 524,288
    const int grid = threads / TPB;           // 2048
    volattn3d_kernel<<<grid, TPB>>>(q, k, v, w_proj, b_proj, out);
}

// round 5
// speedup vs baseline: 1.0983x; 1.0983x over previous
#include <cuda_runtime.h>

// Problem constants (B=1, N=4, C=16, D=64, H=128, W=128)
#define NCTX 4
#define CH   16
#define VOX  (64 * 128 * 128)   // 1,048,576 voxels
#define VPT  2                  // voxels per thread (float2)
#define TPB  256
#define NSM  148
#define CTAS_PER_SM 4
#define GRID (NSM * CTAS_PER_SM)           // 592 persistent CTAs
#define NTILES (VOX / (TPB * VPT))         // 2048 voxel tiles

__global__ __launch_bounds__(TPB, CTAS_PER_SM) void volattn3d_kernel(
    const float* __restrict__ q,      // [C][V]
    const float* __restrict__ k,      // [N][C][V]
    const float* __restrict__ v,      // [N][C][V]
    const float* __restrict__ w_proj, // [C][C]
    const float* __restrict__ b_proj, // [C]
    float* __restrict__ out)          // [C][V]
{
    __shared__ float sw[CH * CH];
    __shared__ float sb[CH];
    {
        int t = threadIdx.x;
        if (t < CH * CH) sw[t] = w_proj[t];
        if (t < CH)      sb[t] = b_proj[t];
    }
    __syncthreads();

    for (int tile = blockIdx.x; tile < NTILES; tile += GRID) {
        const int p = (tile * TPB + threadIdx.x) * VPT;   // base voxel pair
        const float* qp = q + p;
        const float* kp = k + p;
        const float* vp = v + p;

        // ---- scores[n] = (q . k_n), c-outer so q is never array-resident ----
        float2 sc[NCTX];
#pragma unroll
        for (int n = 0; n < NCTX; ++n) sc[n] = make_float2(0.f, 0.f);

#pragma unroll
        for (int c = 0; c < CH; ++c) {
            const float2 qv = __ldcs(reinterpret_cast<const float2*>(qp + c * VOX));
#pragma unroll
            for (int n = 0; n < NCTX; ++n) {
                const float2 kv = __ldcs(reinterpret_cast<const float2*>(kp + (n * CH + c) * VOX));
                sc[n].x = fmaf(qv.x, kv.x, sc[n].x);
                sc[n].y = fmaf(qv.y, kv.y, sc[n].y);
            }
        }
        // scale by 1/sqrt(C) = 0.25
#pragma unroll
        for (int n = 0; n < NCTX; ++n) { sc[n].x *= 0.25f; sc[n].y *= 0.25f; }

        // ---- softmax over n ----
        float2 mx = sc[0];
#pragma unroll
        for (int n = 1; n < NCTX; ++n) {
            mx.x = fmaxf(mx.x, sc[n].x);
            mx.y = fmaxf(mx.y, sc[n].y);
        }
        float2 ssum = make_float2(0.f, 0.f);
#pragma unroll
        for (int n = 0; n < NCTX; ++n) {
            sc[n].x = __expf(sc[n].x - mx.x);
            sc[n].y = __expf(sc[n].y - mx.y);
            ssum.x += sc[n].x;
            ssum.y += sc[n].y;
        }
        const float2 rs = make_float2(__frcp_rn(ssum.x), __frcp_rn(ssum.y));
#pragma unroll
        for (int n = 0; n < NCTX; ++n) { sc[n].x *= rs.x; sc[n].y *= rs.y; }

        // ---- x[c] = sum_n attn[n] * v[n][c] ----
        float2 x[CH];
#pragma unroll
        for (int c = 0; c < CH; ++c) x[c] = make_float2(0.f, 0.f);
#pragma unroll
        for (int n = 0; n < NCTX; ++n) {
#pragma unroll
            for (int c = 0; c < CH; ++c) {
                const float2 vv = __ldcs(reinterpret_cast<const float2*>(vp + (n * CH + c) * VOX));
                x[c].x = fmaf(sc[n].x, vv.x, x[c].x);
                x[c].y = fmaf(sc[n].y, vv.y, x[c].y);
            }
        }

        // ---- out[o] = sum_c w[o][c] * x[c] + b[o] ----
        float* op = out + p;
#pragma unroll
        for (int o = 0; o < CH; ++o) {
            const float bo = sb[o];
            float2 acc = make_float2(bo, bo);
#pragma unroll
            for (int c = 0; c < CH; ++c) {
                const float wv = sw[o * CH + c];
                acc.x = fmaf(wv, x[c].x, acc.x);
                acc.y = fmaf(wv, x[c].y, acc.y);
            }
            __stcs(reinterpret_cast<float2*>(op + o * VOX), acc);
        }
    }
}

extern "C" void kernel_launch(void* const* d_in, const int* in_sizes, int n_in,
                              void* d_out, int out_size) {
    const float* q      = (const float*)d_in[0];
    const float* k      = (const float*)d_in[1];
    const float* v      = (const float*)d_in[2];
    const float* w_proj = (const float*)d_in[3];
    const float* b_proj = (const float*)d_in[4];
    float* out = (float*)d_out;

    volattn3d_kernel<<<GRID, TPB>>>(q, k, v, w_proj, b_proj, out);
}